// round 8
// baseline (speedup 1.0000x reference)
#include <cuda_runtime.h>
#include <cuda_bf16.h>

// Problem constants
#define NB   32
#define NN   8400
#define NCLS 80
#define NCF  (NN * NCLS)       // 672000 scores per batch
#define TOPK 1024
#define CAP  8192
#define NDET 300
#define THRS 0.001f
#define IOUT 0.7f

#define CLO    0.96875f        // high-region lower bound (31/32, exact fp32)
#define CSCAL  8192.0f         // (s-CLO)*2^13 -> 256 coarse bins over hi region
#define NBINS  32768           // fallback-only fine bins
#define HWORDS 16384
#define HSLICES 16
#define NSEG   (HSLICES * 32)  // per-warp private segments per batch = 512
#define SEGCAP 128             // entries per segment (expected ~41)

// ---------------- scratch (device globals; no allocation allowed) ----------
__device__ unsigned int        g_coarse[NB * 256];
__device__ int                 g_done[NB];            // zero-init; self-resetting
__device__ int                 g_thr[NB];
__device__ int                 g_mode[NB];
__device__ int                 g_usehi[NB];
__device__ int                 g_segcnt[NB * NSEG];
__device__ unsigned long long  g_hi[NB * NSEG * SEGCAP];   // 16 MB
__device__ int                 g_cnt[NB];
__device__ unsigned long long  g_cand[NB * CAP];

// coarse hi-region bin (valid only for s > CLO): monotonic in s, 0..255
__device__ __forceinline__ unsigned binhi(float s) {
    unsigned b = (unsigned)(__fmul_rn(__fsub_rn(s, CLO), CSCAL));
    return b > 255u ? 255u : b;
}
// full-range bin (fallback): 0 for masked scores, else monotonic
__device__ __forceinline__ unsigned binlo2(float s) {
    if (!(s > THRS)) return 0u;
    unsigned b = (unsigned)(s * 32768.0f);
    return b > (NBINS - 1) ? (NBINS - 1) : b;
}

// ---------------- kernel 1: fused scan + capture + last-block threshold -----
// grid (HSLICES, NB), 1024 threads. Fast path: 1 ballot per float4.
__global__ void __launch_bounds__(1024) k_scan(const float4* __restrict__ s4) {
    __shared__ unsigned shc[256];
    __shared__ int isLast;
    __shared__ int ovf;
    const int b = blockIdx.y, s = blockIdx.x, t = threadIdx.x;
    const int warp = t >> 5, lane = t & 31;
    if (t < 256) shc[t] = 0;
    if (t == 0) { isLast = 0; ovf = 0; }
    __syncthreads();

    const int perb4 = NCF / 4;                 // 168000
    const int slice = perb4 / HSLICES;         // 10500
    const int ITERS = (slice + 1023) / 1024;   // 11
    const float4* src = s4 + (size_t)b * perb4 + (size_t)s * slice;
    const int eltbase = s * slice;

    const int seg = s * 32 + warp;
    unsigned long long* mybuf = g_hi + ((size_t)(b * NSEG + seg)) * SEGCAP;
    int wcnt = 0;

    for (int o = 0; o < ITERS; o += 4) {
        float4 v[4];
        int    ii[4];
        #pragma unroll
        for (int k = 0; k < 4; k++) {
            ii[k] = (o + k) * 1024 + t;
            v[k] = (o + k < ITERS && ii[k] < slice) ? src[ii[k]]
                                                    : make_float4(0.f, 0.f, 0.f, 0.f);
        }
        #pragma unroll
        for (int k = 0; k < 4; k++) {
            // fast path: one ballot over the whole float4
            float mx = fmaxf(fmaxf(v[k].x, v[k].y), fmaxf(v[k].z, v[k].w));
            unsigned any = __ballot_sync(0xffffffffu, mx > CLO);
            if (any == 0) continue;                       // warp-uniform skip
            float comp[4] = {v[k].x, v[k].y, v[k].z, v[k].w};
            #pragma unroll
            for (int q = 0; q < 4; q++) {
                float sv = comp[q];
                bool pred = (sv > CLO);
                if (pred) atomicAdd(&shc[binhi(sv)], 1u);
                unsigned msk = __ballot_sync(0xffffffffu, pred);
                if (msk) {
                    if (pred) {
                        int p = wcnt + __popc(msk & ((1u << lane) - 1u));
                        if (p < SEGCAP) {
                            unsigned idx = (unsigned)((eltbase + ii[k]) * 4 + q);
                            mybuf[p] = ((unsigned long long)__float_as_uint(sv) << 32)
                                     | (unsigned long long)(~idx);
                        }
                    }
                    wcnt += __popc(msk);
                }
            }
        }
    }
    if (lane == 0) g_segcnt[b * NSEG + seg] = wcnt;   // raw (overflow detectable)

    __syncthreads();
    if (t < 256 && shc[t]) atomicAdd(&g_coarse[b * 256 + t], shc[t]);

    // last block per batch computes the coarse threshold
    __threadfence();
    __syncthreads();
    if (t == 0) {
        int d = atomicAdd(&g_done[b], 1);
        if (d == HSLICES - 1) isLast = 1;
    }
    __syncthreads();
    if (!isLast) return;
    __threadfence();                                  // see all blocks' writes

    if (t < NSEG && g_segcnt[b * NSEG + t] > SEGCAP) atomicOr(&ovf, 1);
    if (t < 256) shc[t] = g_coarse[b * 256 + t];
    __syncthreads();
    if (t == 0) {
        int sel = -1;
        unsigned cum = 0;
        for (int c = 255; c >= 0; c--) {
            cum += shc[c];
            if (cum >= TOPK) { sel = c; break; }
        }
        if (sel < 0) { g_mode[b] = 0; g_usehi[b] = 0; }
        else {
            g_thr[b] = sel;
            g_mode[b] = 1;
            g_usehi[b] = ovf ? 0 : 1;
        }
        g_cnt[b] = 0;
        g_done[b] = 0;                                // reset for next replay
    }
    if (t < 256) g_coarse[b * 256 + t] = 0;           // after copy to shc
}

// ---------------- kernel 2: gated cold path (threshold + collect) -----------
// Runs only when the hi-region fast path failed (never for this workload).
__global__ void __launch_bounds__(1024) k_cold(const float4* __restrict__ s4) {
    const int b = blockIdx.x;
    if (((volatile int*)g_usehi)[b] != 0) return;
    extern __shared__ unsigned sh[];
    __shared__ unsigned co[256];
    const int t = threadIdx.x;
    const int perb4 = NCF / 4;
    const float4* src = s4 + (size_t)b * perb4;
    const int mode = g_mode[b];

    if (mode == 0) {
        // full-range fine histogram to find T
        for (int i = t; i < HWORDS; i += 1024) sh[i] = 0;
        __syncthreads();
        for (int i = t; i < perb4; i += 1024) {
            float4 v = src[i];
            float comp[4] = {v.x, v.y, v.z, v.w};
            #pragma unroll
            for (int q = 0; q < 4; q++) {
                unsigned k = binlo2(comp[q]);
                atomicAdd(&sh[k >> 1], 1u << ((k & 1) * 16));
            }
        }
        __syncthreads();
        if (t < 256) {
            unsigned sum = 0;
            for (int k = 0; k < 64; k++) {
                unsigned m = sh[t * 64 + k];
                sum += (m & 0xFFFFu) + (m >> 16);
            }
            co[t] = sum;
        }
        __syncthreads();
        if (t == 0) {
            unsigned h0 = sh[0] & 0xFFFFu;
            int sel = -1; unsigned cum = 0, cums = 0;
            for (int c = 255; c >= 0; c--) {
                unsigned cc = co[c] - (c == 0 ? h0 : 0u);
                if (cum + cc >= TOPK) { sel = c; cums = cum; break; }
                cum += cc;
            }
            int T = 1;
            if (sel >= 0) {
                unsigned cum2 = cums;
                int lo = (sel == 0) ? 1 : 0;
                for (int fb = 127; fb >= lo; fb--) {
                    int bin = (sel << 7) + fb;
                    unsigned m = sh[bin >> 1];
                    unsigned cc = (bin & 1) ? (m >> 16) : (m & 0xFFFFu);
                    cum2 += cc;
                    if (cum2 >= TOPK) { T = bin; break; }
                }
            }
            g_thr[b] = T;
        }
        __syncthreads();
    }

    // collect pass
    const unsigned T = (unsigned)g_thr[b];
    for (int i = t; i < perb4; i += 1024) {
        float4 v = src[i];
        float comp[4] = {v.x, v.y, v.z, v.w};
        #pragma unroll
        for (int q = 0; q < 4; q++) {
            float sv = comp[q];
            bool acc = mode ? (sv > CLO && binhi(sv) >= T) : (binlo2(sv) >= T);
            if (acc) {
                int p = atomicAdd(&g_cnt[b], 1);
                if (p < CAP) {
                    unsigned idx = (unsigned)(i * 4 + q);
                    g_cand[b * CAP + p] =
                        ((unsigned long long)__float_as_uint(sv) << 32)
                        | (unsigned long long)(~idx);
                }
            }
        }
    }
}

// bitonic register step: element index i, phase k2, distance j (<32)
__device__ __forceinline__ unsigned long long bstep(
    unsigned long long v, int i, int k2, int j) {
    unsigned long long o = __shfl_xor_sync(0xffffffffu, v, j);
    bool keepmax = (((i & k2) == 0) == ((i & j) == 0));
    unsigned long long mx = v > o ? v : o;
    unsigned long long mn = v > o ? o : v;
    return keepmax ? mx : mn;
}

// ---------------- kernel 3: fused filter + sort + per-class NMS + output ----
// key u64 = (float_bits << 32) | ~flat_idx, descending ->
// score desc, flat idx ascending on ties (matches lax.top_k stability).
// Cross-class IoU is exactly 0 (class offset gap), so global greedy ==
// independent per-class greedy in global-rank order. IoU ops identical to
// reference: offset coords, strict > 0.7, __f*_rn arithmetic.
__global__ void __launch_bounds__(1024) k_sortnms(const float4* __restrict__ boxes,
                                                  float* __restrict__ out) {
    extern __shared__ unsigned long long sm[];       // CAP u64 = 64 KB
    __shared__ int scnt;
    __shared__ float4 sbox[TOPK];                    // 16 KB
    __shared__ float sy1[TOPK], sx1[TOPK], sy2[TOPK], sx2[TOPK], sa[TOPK];
    __shared__ float ssc[TOPK];
    __shared__ short scls[TOPK];
    __shared__ unsigned short wcount[NCLS * 32];
    __shared__ unsigned short wbase [NCLS * 32];
    __shared__ unsigned short ctot[NCLS];
    __shared__ unsigned short cstart[NCLS + 1];
    __shared__ unsigned short list[TOPK];
    __shared__ unsigned char  skept[TOPK];
    __shared__ unsigned kw[32];
    __shared__ int kpref[33];

    int b = blockIdx.x;
    int t = threadIdx.x;
    int warp = t >> 5, lane = t & 31;
    if (t == 0) scnt = 0;
    __syncthreads();

    // ---- stage candidates into smem ----
    if (g_usehi[b]) {
        const unsigned T = (unsigned)g_thr[b];
        #pragma unroll 1
        for (int sg = warp * 16; sg < warp * 16 + 16; sg++) {
            int cnt = g_segcnt[b * NSEG + sg];
            if (cnt > SEGCAP) cnt = SEGCAP;
            const unsigned long long* buf = g_hi + ((size_t)(b * NSEG + sg)) * SEGCAP;
            for (int off = lane; off < cnt; off += 32) {
                unsigned long long kk = buf[off];
                float sv = __uint_as_float((unsigned)(kk >> 32));
                if (binhi(sv) >= T) {
                    int p = atomicAdd(&scnt, 1);
                    if (p < CAP) sm[p] = kk;
                }
            }
        }
    } else {
        int cnt = g_cnt[b]; if (cnt > CAP) cnt = CAP;
        for (int i = t; i < cnt; i += 1024) sm[i] = g_cand[b * CAP + i];
        if (t == 0) scnt = cnt;
    }
    __syncthreads();
    int cnt = scnt; if (cnt > CAP) cnt = CAP;
    int n2 = 2048;
    while (n2 < cnt) n2 <<= 1;
    for (int i = t; i < n2; i += 1024) if (i >= cnt) sm[i] = 0ull;
    __syncthreads();

    // ---- bitonic sort ----
    if (n2 == 2048) {
        const int i1 = t, i2 = t + 1024;
        unsigned long long a = sm[i1], c = sm[i2];
        #pragma unroll
        for (int k2 = 2; k2 <= 32; k2 <<= 1)
            #pragma unroll
            for (int j = k2 >> 1; j >= 1; j >>= 1) {
                a = bstep(a, i1, k2, j);
                c = bstep(c, i2, k2, j);
            }
        sm[i1] = a; sm[i2] = c;
        __syncthreads();
        #pragma unroll
        for (int k2 = 64; k2 <= 2048; k2 <<= 1) {
            for (int j = k2 >> 1; j >= 32; j >>= 1) {
                #pragma unroll
                for (int e = 0; e < 2; e++) {
                    int i = t + e * 1024;
                    int ixj = i ^ j;
                    if (ixj > i) {
                        unsigned long long x = sm[i], y = sm[ixj];
                        bool desc = ((i & k2) == 0);
                        if (desc ? (x < y) : (x > y)) { sm[i] = y; sm[ixj] = x; }
                    }
                }
                __syncthreads();
            }
            a = sm[i1]; c = sm[i2];
            #pragma unroll
            for (int j = 16; j >= 1; j >>= 1) {
                a = bstep(a, i1, k2, j);
                c = bstep(c, i2, k2, j);
            }
            sm[i1] = a; sm[i2] = c;
            __syncthreads();
        }
    } else {
        for (int k2 = 2; k2 <= n2; k2 <<= 1) {
            for (int j = k2 >> 1; j > 0; j >>= 1) {
                for (int i = t; i < n2; i += 1024) {
                    int ixj = i ^ j;
                    if (ixj > i) {
                        unsigned long long x = sm[i], y = sm[ixj];
                        bool desc = ((i & k2) == 0);
                        if (desc ? (x < y) : (x > y)) { sm[i] = y; sm[ixj] = x; }
                    }
                }
                __syncthreads();
            }
        }
    }

    // ---- gather top-1024 boxes + build offset coords ----
    {
        unsigned long long kk = sm[t];
        unsigned keyhi = (unsigned)(kk >> 32);
        float4 bx = make_float4(0.f, 0.f, 0.f, 0.f);
        int cls = 0; float sc = 0.f;
        if (keyhi != 0) {
            unsigned idx = ~(unsigned)(kk & 0xFFFFFFFFull);
            int n = (int)(idx / NCLS);
            cls = (int)(idx % NCLS);
            sc = __uint_as_float(keyhi);
            bx = boxes[b * NN + n];
        }
        sbox[t] = bx; scls[t] = (short)cls; ssc[t] = sc;
        float off = (float)cls * 4096.0f;            // exact in fp32
        float y1 = __fadd_rn(bx.x, off);
        float x1 = __fadd_rn(bx.y, off);
        float y2 = __fadd_rn(bx.z, off);
        float x2 = __fadd_rn(bx.w, off);
        sy1[t] = y1; sx1[t] = x1; sy2[t] = y2; sx2[t] = x2;
        sa[t] = __fmul_rn(__fadd_rn(__fsub_rn(x2, x1), 1.0f),
                          __fadd_rn(__fsub_rn(y2, y1), 1.0f));
    }
    float sc = ssc[t];
    int c = scls[t];
    bool valid = (sc > THRS);
    unsigned bal = __ballot_sync(0xffffffff, valid);
    if (lane == 0) kw[warp] = bal;
    for (int i = t; i < NCLS * 32; i += 1024) wcount[i] = 0;
    skept[t] = 1;
    __syncthreads();

    // ---- stable per-class list build ----
    int cc = valid ? c : 0x7FFF;
    unsigned mm = __match_any_sync(0xffffffffu, cc);
    int rank = __popc(mm & ((1u << lane) - 1u));
    int ldr = __ffs(mm) - 1;
    if (valid && lane == ldr) wcount[cc * 32 + warp] = (unsigned short)__popc(mm);
    __syncthreads();
    if (t < NCLS) {
        int run = 0;
        for (int w = 0; w < 32; w++) {
            int v = wcount[t * 32 + w];
            wbase[t * 32 + w] = (unsigned short)run;
            run += v;
        }
        ctot[t] = (unsigned short)run;
    }
    __syncthreads();
    if (t == 0) {
        int s = 0;
        for (int c2 = 0; c2 < NCLS; c2++) { cstart[c2] = (unsigned short)s; s += ctot[c2]; }
        cstart[NCLS] = (unsigned short)s;
    }
    __syncthreads();
    if (valid) list[cstart[cc] + wbase[cc * 32 + warp] + rank] = (unsigned short)t;
    __syncthreads();

    // ---- per-class greedy (one warp per class, strided) ----
    for (int c2 = warp; c2 < NCLS; c2 += 32) {
        int m = ctot[c2];
        if (m < 2) continue;
        int base = cstart[c2];
        if (m <= 32) {
            int tj = 0; bool kept = false;
            float jy1 = 0, jx1 = 0, jy2 = 0, jx2 = 0, ja = 0;
            if (lane < m) {
                tj = list[base + lane];
                jy1 = sy1[tj]; jx1 = sx1[tj]; jy2 = sy2[tj]; jx2 = sx2[tj]; ja = sa[tj];
                kept = true;
            }
            for (int i = 0; i < m - 1; i++) {
                unsigned alive = __ballot_sync(0xffffffffu, kept);
                if (!((alive >> i) & 1u)) continue;
                int ti = list[base + i];
                float iy1 = sy1[ti], ix1 = sx1[ti], iy2 = sy2[ti], ix2 = sx2[ti], ia = sa[ti];
                if (lane > i && kept) {
                    float yy1 = fmaxf(iy1, jy1);
                    float xx1 = fmaxf(ix1, jx1);
                    float yy2 = fminf(iy2, jy2);
                    float xx2 = fminf(ix2, jx2);
                    float ww = fmaxf(0.0f, __fadd_rn(__fsub_rn(xx2, xx1), 1.0f));
                    float hh = fmaxf(0.0f, __fadd_rn(__fsub_rn(yy2, yy1), 1.0f));
                    float inter = __fmul_rn(ww, hh);
                    float iou = __fdiv_rn(inter, __fsub_rn(__fadd_rn(ia, ja), inter));
                    if (iou > IOUT) kept = false;
                }
            }
            if (lane < m && !kept) atomicAnd(&kw[tj >> 5], ~(1u << (tj & 31)));
        } else {
            for (int i = 0; i < m - 1; i++) {
                __syncwarp();
                if (!skept[base + i]) continue;
                int ti = list[base + i];
                float iy1 = sy1[ti], ix1 = sx1[ti], iy2 = sy2[ti], ix2 = sx2[ti], ia = sa[ti];
                for (int k = i + 1 + lane; k < m; k += 32) {
                    if (skept[base + k]) {
                        int tk = list[base + k];
                        float yy1 = fmaxf(iy1, sy1[tk]);
                        float xx1 = fmaxf(ix1, sx1[tk]);
                        float yy2 = fminf(iy2, sy2[tk]);
                        float xx2 = fminf(ix2, sx2[tk]);
                        float ww = fmaxf(0.0f, __fadd_rn(__fsub_rn(xx2, xx1), 1.0f));
                        float hh = fmaxf(0.0f, __fadd_rn(__fsub_rn(yy2, yy1), 1.0f));
                        float inter = __fmul_rn(ww, hh);
                        float iou = __fdiv_rn(inter, __fsub_rn(__fadd_rn(ia, sa[tk]), inter));
                        if (iou > IOUT) skept[base + k] = 0;
                    }
                }
            }
            __syncwarp();
            for (int k = lane; k < m; k += 32)
                if (!skept[base + k]) {
                    int tk = list[base + k];
                    atomicAnd(&kw[tk >> 5], ~(1u << (tk & 31)));
                }
        }
    }
    __syncthreads();

    // ---- ranking + output ----
    if (t < 32) {
        unsigned my = kw[t];
        int p = __popc(my);
        int x = p;
        #pragma unroll
        for (int o = 1; o < 32; o <<= 1) {
            int y = __shfl_up_sync(0xffffffff, x, o);
            if (t >= o) x += y;
        }
        kpref[t] = x - p;
        if (t == 31) kpref[32] = x;
    }
    __syncthreads();

    int w = t >> 5, l = t & 31;
    unsigned kwv = kw[w];
    bool kept = (kwv >> l) & 1u;
    unsigned lowm = (l == 0) ? 0u : ((1u << l) - 1u);
    int TKall = kpref[32];

    int slot = -1;
    float oscore = 0.0f;
    if (kept) {
        int kr = kpref[w] + __popc(kwv & lowm);
        if (kr < NDET) { slot = kr; oscore = sc; }
    } else {
        int sr = (w << 5) - kpref[w] + __popc((~kwv) & lowm);
        int s2 = TKall + sr;
        if (s2 < NDET) { slot = s2; oscore = 0.0f; }
    }

    // output layout (float32): boxes[32,300,4] | scores[32,300] | labels[32,300] | n_valid[32,1]
    if (slot >= 0) {
        float4 bx = sbox[t];
        float* ob = out + ((size_t)b * NDET + slot) * 4;
        ob[0] = bx.x; ob[1] = bx.y; ob[2] = bx.z; ob[3] = bx.w;
        out[NB * NDET * 4 + b * NDET + slot] = oscore;
        out[NB * NDET * 5 + b * NDET + slot] = (float)c;
    }
    if (t == 0)
        out[NB * NDET * 6 + b] = (float)(TKall < NDET ? TKall : NDET);
}

// ---------------- launch ----------------------------------------------------
extern "C" void kernel_launch(void* const* d_in, const int* in_sizes, int n_in,
                              void* d_out, int out_size) {
    const float* boxes  = (const float*)d_in[0];
    const float* scores = (const float*)d_in[1];
    if (n_in >= 2 && in_sizes[0] > in_sizes[1]) {
        boxes  = (const float*)d_in[1];
        scores = (const float*)d_in[0];
    }
    float* out = (float*)d_out;

    cudaFuncSetAttribute(k_cold,    cudaFuncAttributeMaxDynamicSharedMemorySize, HWORDS * 4);
    cudaFuncSetAttribute(k_sortnms, cudaFuncAttributeMaxDynamicSharedMemorySize, CAP * 8);

    k_scan   <<<dim3(HSLICES, NB), 1024>>>((const float4*)scores);
    k_cold   <<<NB, 1024, HWORDS * 4>>>((const float4*)scores);
    k_sortnms<<<NB, 1024, CAP * 8>>>((const float4*)boxes, out);
}

// round 9
// speedup vs baseline: 1.1494x; 1.1494x over previous
#include <cuda_runtime.h>
#include <cuda_bf16.h>

// Problem constants
#define NB   32
#define NN   8400
#define NCLS 80
#define NCF  (NN * NCLS)       // 672000 scores per batch
#define TOPK 1024
#define CAP  8192
#define NDET 300
#define THRS 0.001f
#define IOUT 0.7f

#define CLO    0.96875f        // high-region lower bound (31/32, exact fp32)
#define CSCAL  8192.0f         // (s-CLO)*2^13 -> 256 coarse bins over hi region
#define NBINS  32768           // fallback-only fine bins
#define HWORDS 16384
#define HSLICES 16
#define NSEG   (HSLICES * 32)  // per-warp private segments per batch = 512
#define SEGCAP 128             // entries per segment (expected ~41)

// ---------------- scratch (device globals; no allocation allowed) ----------
__device__ unsigned int        g_coarse[NB * 256];
__device__ int                 g_done[NB];            // zero-init; self-resetting
__device__ int                 g_thr[NB];
__device__ int                 g_mode[NB];
__device__ int                 g_usehi[NB];
__device__ int                 g_segcnt[NB * NSEG];
__device__ unsigned long long  g_hi[NB * NSEG * SEGCAP];   // 16 MB
__device__ int                 g_cnt[NB];
__device__ unsigned long long  g_cand[NB * CAP];

// coarse hi-region bin (valid only for s > CLO): monotonic in s, 0..255
__device__ __forceinline__ unsigned binhi(float s) {
    unsigned b = (unsigned)(__fmul_rn(__fsub_rn(s, CLO), CSCAL));
    return b > 255u ? 255u : b;
}
// full-range bin (fallback): 0 for masked scores, else monotonic
__device__ __forceinline__ unsigned binlo2(float s) {
    if (!(s > THRS)) return 0u;
    unsigned b = (unsigned)(s * 32768.0f);
    return b > (NBINS - 1) ? (NBINS - 1) : b;
}

// ---------------- kernel 1: fused scan + capture + last-block threshold -----
// grid (HSLICES, NB), 1024 threads. No ballots: per-warp smem counter for
// slot allocation (segment order irrelevant -- sort canonicalizes; keys unique).
__global__ void __launch_bounds__(1024) k_scan(const float4* __restrict__ s4) {
    __shared__ unsigned shc[256];
    __shared__ int wctr[32];
    __shared__ int isLast;
    __shared__ int ovf;
    const int b = blockIdx.y, s = blockIdx.x, t = threadIdx.x;
    const int warp = t >> 5, lane = t & 31;
    if (t < 256) shc[t] = 0;
    if (t < 32) wctr[t] = 0;
    if (t == 0) { isLast = 0; ovf = 0; }
    __syncthreads();

    const int perb4 = NCF / 4;                 // 168000
    const int slice = perb4 / HSLICES;         // 10500
    const int ITERS = (slice + 1023) / 1024;   // 11
    const float4* src = s4 + (size_t)b * perb4 + (size_t)s * slice;
    const int eltbase = s * slice;

    const int seg = s * 32 + warp;
    unsigned long long* mybuf = g_hi + ((size_t)(b * NSEG + seg)) * SEGCAP;

    for (int o = 0; o < ITERS; o += 4) {
        float4 v[4];
        int    ii[4];
        #pragma unroll
        for (int k = 0; k < 4; k++) {
            ii[k] = (o + k) * 1024 + t;
            v[k] = (o + k < ITERS && ii[k] < slice) ? src[ii[k]]
                                                    : make_float4(0.f, 0.f, 0.f, 0.f);
        }
        #pragma unroll
        for (int k = 0; k < 4; k++) {
            // per-thread fast reject: one compare on the max of 4
            float mx = fmaxf(fmaxf(v[k].x, v[k].y), fmaxf(v[k].z, v[k].w));
            if (!(mx > CLO)) continue;
            float comp[4] = {v[k].x, v[k].y, v[k].z, v[k].w};
            #pragma unroll
            for (int q = 0; q < 4; q++) {
                float sv = comp[q];
                if (sv > CLO) {
                    atomicAdd(&shc[binhi(sv)], 1u);
                    int p = atomicAdd(&wctr[warp], 1);
                    if (p < SEGCAP) {
                        unsigned idx = (unsigned)((eltbase + ii[k]) * 4 + q);
                        mybuf[p] = ((unsigned long long)__float_as_uint(sv) << 32)
                                 | (unsigned long long)(~idx);
                    }
                }
            }
        }
    }
    __syncthreads();
    if (t < 32) g_segcnt[b * NSEG + s * 32 + t] = wctr[t];  // raw (overflow detectable)
    if (t < 256 && shc[t]) atomicAdd(&g_coarse[b * 256 + t], shc[t]);

    // last block per batch computes the coarse threshold
    __threadfence();
    __syncthreads();
    if (t == 0) {
        int d = atomicAdd(&g_done[b], 1);
        if (d == HSLICES - 1) isLast = 1;
    }
    __syncthreads();
    if (!isLast) return;
    __threadfence();                                  // see all blocks' writes

    if (t < NSEG && g_segcnt[b * NSEG + t] > SEGCAP) atomicOr(&ovf, 1);
    if (t < 256) shc[t] = g_coarse[b * 256 + t];
    __syncthreads();
    if (t == 0) {
        int sel = -1;
        unsigned cum = 0;
        for (int c = 255; c >= 0; c--) {
            cum += shc[c];
            if (cum >= TOPK) { sel = c; break; }
        }
        if (sel < 0) { g_mode[b] = 0; g_usehi[b] = 0; }
        else {
            g_thr[b] = sel;
            g_mode[b] = 1;
            g_usehi[b] = ovf ? 0 : 1;
        }
        g_cnt[b] = 0;
        g_done[b] = 0;                                // reset for next replay
    }
    if (t < 256) g_coarse[b * 256 + t] = 0;           // after copy to shc
}

// ---------------- kernel 2: gated cold path (threshold + collect) -----------
// Runs only when the hi-region fast path failed (never for this workload).
__global__ void __launch_bounds__(1024) k_cold(const float4* __restrict__ s4) {
    const int b = blockIdx.x;
    if (((volatile int*)g_usehi)[b] != 0) return;
    extern __shared__ unsigned sh[];
    __shared__ unsigned co[256];
    const int t = threadIdx.x;
    const int perb4 = NCF / 4;
    const float4* src = s4 + (size_t)b * perb4;
    const int mode = g_mode[b];

    if (mode == 0) {
        // full-range fine histogram to find T
        for (int i = t; i < HWORDS; i += 1024) sh[i] = 0;
        __syncthreads();
        for (int i = t; i < perb4; i += 1024) {
            float4 v = src[i];
            float comp[4] = {v.x, v.y, v.z, v.w};
            #pragma unroll
            for (int q = 0; q < 4; q++) {
                unsigned k = binlo2(comp[q]);
                atomicAdd(&sh[k >> 1], 1u << ((k & 1) * 16));
            }
        }
        __syncthreads();
        if (t < 256) {
            unsigned sum = 0;
            for (int k = 0; k < 64; k++) {
                unsigned m = sh[t * 64 + k];
                sum += (m & 0xFFFFu) + (m >> 16);
            }
            co[t] = sum;
        }
        __syncthreads();
        if (t == 0) {
            unsigned h0 = sh[0] & 0xFFFFu;
            int sel = -1; unsigned cum = 0, cums = 0;
            for (int c = 255; c >= 0; c--) {
                unsigned cc = co[c] - (c == 0 ? h0 : 0u);
                if (cum + cc >= TOPK) { sel = c; cums = cum; break; }
                cum += cc;
            }
            int T = 1;
            if (sel >= 0) {
                unsigned cum2 = cums;
                int lo = (sel == 0) ? 1 : 0;
                for (int fb = 127; fb >= lo; fb--) {
                    int bin = (sel << 7) + fb;
                    unsigned m = sh[bin >> 1];
                    unsigned cc = (bin & 1) ? (m >> 16) : (m & 0xFFFFu);
                    cum2 += cc;
                    if (cum2 >= TOPK) { T = bin; break; }
                }
            }
            g_thr[b] = T;
        }
        __syncthreads();
    }

    // collect pass
    const unsigned T = (unsigned)g_thr[b];
    for (int i = t; i < perb4; i += 1024) {
        float4 v = src[i];
        float comp[4] = {v.x, v.y, v.z, v.w};
        #pragma unroll
        for (int q = 0; q < 4; q++) {
            float sv = comp[q];
            bool acc = mode ? (sv > CLO && binhi(sv) >= T) : (binlo2(sv) >= T);
            if (acc) {
                int p = atomicAdd(&g_cnt[b], 1);
                if (p < CAP) {
                    unsigned idx = (unsigned)(i * 4 + q);
                    g_cand[b * CAP + p] =
                        ((unsigned long long)__float_as_uint(sv) << 32)
                        | (unsigned long long)(~idx);
                }
            }
        }
    }
}

// bitonic register step: element index i, phase k2, distance j (<32)
__device__ __forceinline__ unsigned long long bstep(
    unsigned long long v, int i, int k2, int j) {
    unsigned long long o = __shfl_xor_sync(0xffffffffu, v, j);
    bool keepmax = (((i & k2) == 0) == ((i & j) == 0));
    unsigned long long mx = v > o ? v : o;
    unsigned long long mn = v > o ? o : v;
    return keepmax ? mx : mn;
}

// ---------------- kernel 3: fused filter + sort + per-class NMS + output ----
// key u64 = (float_bits << 32) | ~flat_idx, descending ->
// score desc, flat idx ascending on ties (matches lax.top_k stability).
// Cross-class IoU is exactly 0 (class offset gap), so global greedy ==
// independent per-class greedy in global-rank order. IoU ops identical to
// reference: offset coords, strict > 0.7, __f*_rn arithmetic.
__global__ void __launch_bounds__(1024) k_sortnms(const float4* __restrict__ boxes,
                                                  float* __restrict__ out) {
    extern __shared__ unsigned long long sm[];       // CAP u64 = 64 KB
    __shared__ int scnt;
    __shared__ float4 sbox[TOPK];                    // 16 KB
    __shared__ float sy1[TOPK], sx1[TOPK], sy2[TOPK], sx2[TOPK], sa[TOPK];
    __shared__ float ssc[TOPK];
    __shared__ short scls[TOPK];
    __shared__ unsigned short wcount[NCLS * 32];
    __shared__ unsigned short wbase [NCLS * 32];
    __shared__ unsigned short ctot[NCLS];
    __shared__ unsigned short cstart[NCLS + 1];
    __shared__ unsigned short list[TOPK];
    __shared__ unsigned char  skept[TOPK];
    __shared__ unsigned kw[32];
    __shared__ int kpref[33];

    int b = blockIdx.x;
    int t = threadIdx.x;
    int warp = t >> 5, lane = t & 31;
    if (t == 0) scnt = 0;
    __syncthreads();

    // ---- stage candidates into smem ----
    if (g_usehi[b]) {
        const unsigned T = (unsigned)g_thr[b];
        #pragma unroll 1
        for (int sg = warp * 16; sg < warp * 16 + 16; sg++) {
            int cnt = g_segcnt[b * NSEG + sg];
            if (cnt > SEGCAP) cnt = SEGCAP;
            const unsigned long long* buf = g_hi + ((size_t)(b * NSEG + sg)) * SEGCAP;
            for (int off = lane; off < cnt; off += 32) {
                unsigned long long kk = buf[off];
                float sv = __uint_as_float((unsigned)(kk >> 32));
                if (binhi(sv) >= T) {
                    int p = atomicAdd(&scnt, 1);
                    if (p < CAP) sm[p] = kk;
                }
            }
        }
    } else {
        int cnt = g_cnt[b]; if (cnt > CAP) cnt = CAP;
        for (int i = t; i < cnt; i += 1024) sm[i] = g_cand[b * CAP + i];
        if (t == 0) scnt = cnt;
    }
    __syncthreads();
    int cnt = scnt; if (cnt > CAP) cnt = CAP;
    int n2 = 2048;
    while (n2 < cnt) n2 <<= 1;
    for (int i = t; i < n2; i += 1024) if (i >= cnt) sm[i] = 0ull;
    __syncthreads();

    // ---- bitonic sort ----
    if (n2 == 2048) {
        const int i1 = t, i2 = t + 1024;
        unsigned long long a = sm[i1], c = sm[i2];
        #pragma unroll
        for (int k2 = 2; k2 <= 32; k2 <<= 1)
            #pragma unroll
            for (int j = k2 >> 1; j >= 1; j >>= 1) {
                a = bstep(a, i1, k2, j);
                c = bstep(c, i2, k2, j);
            }
        sm[i1] = a; sm[i2] = c;
        __syncthreads();
        #pragma unroll
        for (int k2 = 64; k2 <= 2048; k2 <<= 1) {
            for (int j = k2 >> 1; j >= 32; j >>= 1) {
                #pragma unroll
                for (int e = 0; e < 2; e++) {
                    int i = t + e * 1024;
                    int ixj = i ^ j;
                    if (ixj > i) {
                        unsigned long long x = sm[i], y = sm[ixj];
                        bool desc = ((i & k2) == 0);
                        if (desc ? (x < y) : (x > y)) { sm[i] = y; sm[ixj] = x; }
                    }
                }
                __syncthreads();
            }
            a = sm[i1]; c = sm[i2];
            #pragma unroll
            for (int j = 16; j >= 1; j >>= 1) {
                a = bstep(a, i1, k2, j);
                c = bstep(c, i2, k2, j);
            }
            sm[i1] = a; sm[i2] = c;
            __syncthreads();
        }
    } else {
        for (int k2 = 2; k2 <= n2; k2 <<= 1) {
            for (int j = k2 >> 1; j > 0; j >>= 1) {
                for (int i = t; i < n2; i += 1024) {
                    int ixj = i ^ j;
                    if (ixj > i) {
                        unsigned long long x = sm[i], y = sm[ixj];
                        bool desc = ((i & k2) == 0);
                        if (desc ? (x < y) : (x > y)) { sm[i] = y; sm[ixj] = x; }
                    }
                }
                __syncthreads();
            }
        }
    }

    // ---- gather top-1024 boxes + build offset coords ----
    {
        unsigned long long kk = sm[t];
        unsigned keyhi = (unsigned)(kk >> 32);
        float4 bx = make_float4(0.f, 0.f, 0.f, 0.f);
        int cls = 0; float sc = 0.f;
        if (keyhi != 0) {
            unsigned idx = ~(unsigned)(kk & 0xFFFFFFFFull);
            int n = (int)(idx / NCLS);
            cls = (int)(idx % NCLS);
            sc = __uint_as_float(keyhi);
            bx = boxes[b * NN + n];
        }
        sbox[t] = bx; scls[t] = (short)cls; ssc[t] = sc;
        float off = (float)cls * 4096.0f;            // exact in fp32
        float y1 = __fadd_rn(bx.x, off);
        float x1 = __fadd_rn(bx.y, off);
        float y2 = __fadd_rn(bx.z, off);
        float x2 = __fadd_rn(bx.w, off);
        sy1[t] = y1; sx1[t] = x1; sy2[t] = y2; sx2[t] = x2;
        sa[t] = __fmul_rn(__fadd_rn(__fsub_rn(x2, x1), 1.0f),
                          __fadd_rn(__fsub_rn(y2, y1), 1.0f));
    }
    float sc = ssc[t];
    int c = scls[t];
    bool valid = (sc > THRS);
    unsigned bal = __ballot_sync(0xffffffff, valid);
    if (lane == 0) kw[warp] = bal;
    for (int i = t; i < NCLS * 32; i += 1024) wcount[i] = 0;
    skept[t] = 1;
    __syncthreads();

    // ---- stable per-class list build ----
    int cc = valid ? c : 0x7FFF;
    unsigned mm = __match_any_sync(0xffffffffu, cc);
    int rank = __popc(mm & ((1u << lane) - 1u));
    int ldr = __ffs(mm) - 1;
    if (valid && lane == ldr) wcount[cc * 32 + warp] = (unsigned short)__popc(mm);
    __syncthreads();
    if (t < NCLS) {
        int run = 0;
        for (int w = 0; w < 32; w++) {
            int v = wcount[t * 32 + w];
            wbase[t * 32 + w] = (unsigned short)run;
            run += v;
        }
        ctot[t] = (unsigned short)run;
    }
    __syncthreads();
    if (t == 0) {
        int s = 0;
        for (int c2 = 0; c2 < NCLS; c2++) { cstart[c2] = (unsigned short)s; s += ctot[c2]; }
        cstart[NCLS] = (unsigned short)s;
    }
    __syncthreads();
    if (valid) list[cstart[cc] + wbase[cc * 32 + warp] + rank] = (unsigned short)t;
    __syncthreads();

    // ---- per-class greedy (one warp per class, strided) ----
    for (int c2 = warp; c2 < NCLS; c2 += 32) {
        int m = ctot[c2];
        if (m < 2) continue;
        int base = cstart[c2];
        if (m <= 32) {
            int tj = 0; bool kept = false;
            float jy1 = 0, jx1 = 0, jy2 = 0, jx2 = 0, ja = 0;
            if (lane < m) {
                tj = list[base + lane];
                jy1 = sy1[tj]; jx1 = sx1[tj]; jy2 = sy2[tj]; jx2 = sx2[tj]; ja = sa[tj];
                kept = true;
            }
            for (int i = 0; i < m - 1; i++) {
                unsigned alive = __ballot_sync(0xffffffffu, kept);
                if (!((alive >> i) & 1u)) continue;
                int ti = list[base + i];
                float iy1 = sy1[ti], ix1 = sx1[ti], iy2 = sy2[ti], ix2 = sx2[ti], ia = sa[ti];
                if (lane > i && kept) {
                    float yy1 = fmaxf(iy1, jy1);
                    float xx1 = fmaxf(ix1, jx1);
                    float yy2 = fminf(iy2, jy2);
                    float xx2 = fminf(ix2, jx2);
                    float ww = fmaxf(0.0f, __fadd_rn(__fsub_rn(xx2, xx1), 1.0f));
                    float hh = fmaxf(0.0f, __fadd_rn(__fsub_rn(yy2, yy1), 1.0f));
                    float inter = __fmul_rn(ww, hh);
                    float iou = __fdiv_rn(inter, __fsub_rn(__fadd_rn(ia, ja), inter));
                    if (iou > IOUT) kept = false;
                }
            }
            if (lane < m && !kept) atomicAnd(&kw[tj >> 5], ~(1u << (tj & 31)));
        } else {
            for (int i = 0; i < m - 1; i++) {
                __syncwarp();
                if (!skept[base + i]) continue;
                int ti = list[base + i];
                float iy1 = sy1[ti], ix1 = sx1[ti], iy2 = sy2[ti], ix2 = sx2[ti], ia = sa[ti];
                for (int k = i + 1 + lane; k < m; k += 32) {
                    if (skept[base + k]) {
                        int tk = list[base + k];
                        float yy1 = fmaxf(iy1, sy1[tk]);
                        float xx1 = fmaxf(ix1, sx1[tk]);
                        float yy2 = fminf(iy2, sy2[tk]);
                        float xx2 = fminf(ix2, sx2[tk]);
                        float ww = fmaxf(0.0f, __fadd_rn(__fsub_rn(xx2, xx1), 1.0f));
                        float hh = fmaxf(0.0f, __fadd_rn(__fsub_rn(yy2, yy1), 1.0f));
                        float inter = __fmul_rn(ww, hh);
                        float iou = __fdiv_rn(inter, __fsub_rn(__fadd_rn(ia, sa[tk]), inter));
                        if (iou > IOUT) skept[base + k] = 0;
                    }
                }
            }
            __syncwarp();
            for (int k = lane; k < m; k += 32)
                if (!skept[base + k]) {
                    int tk = list[base + k];
                    atomicAnd(&kw[tk >> 5], ~(1u << (tk & 31)));
                }
        }
    }
    __syncthreads();

    // ---- ranking + output ----
    if (t < 32) {
        unsigned my = kw[t];
        int p = __popc(my);
        int x = p;
        #pragma unroll
        for (int o = 1; o < 32; o <<= 1) {
            int y = __shfl_up_sync(0xffffffff, x, o);
            if (t >= o) x += y;
        }
        kpref[t] = x - p;
        if (t == 31) kpref[32] = x;
    }
    __syncthreads();

    int w = t >> 5, l = t & 31;
    unsigned kwv = kw[w];
    bool kept = (kwv >> l) & 1u;
    unsigned lowm = (l == 0) ? 0u : ((1u << l) - 1u);
    int TKall = kpref[32];

    int slot = -1;
    float oscore = 0.0f;
    if (kept) {
        int kr = kpref[w] + __popc(kwv & lowm);
        if (kr < NDET) { slot = kr; oscore = sc; }
    } else {
        int sr = (w << 5) - kpref[w] + __popc((~kwv) & lowm);
        int s2 = TKall + sr;
        if (s2 < NDET) { slot = s2; oscore = 0.0f; }
    }

    // output layout (float32): boxes[32,300,4] | scores[32,300] | labels[32,300] | n_valid[32,1]
    if (slot >= 0) {
        float4 bx = sbox[t];
        float* ob = out + ((size_t)b * NDET + slot) * 4;
        ob[0] = bx.x; ob[1] = bx.y; ob[2] = bx.z; ob[3] = bx.w;
        out[NB * NDET * 4 + b * NDET + slot] = oscore;
        out[NB * NDET * 5 + b * NDET + slot] = (float)c;
    }
    if (t == 0)
        out[NB * NDET * 6 + b] = (float)(TKall < NDET ? TKall : NDET);
}

// ---------------- launch ----------------------------------------------------
extern "C" void kernel_launch(void* const* d_in, const int* in_sizes, int n_in,
                              void* d_out, int out_size) {
    const float* boxes  = (const float*)d_in[0];
    const float* scores = (const float*)d_in[1];
    if (n_in >= 2 && in_sizes[0] > in_sizes[1]) {
        boxes  = (const float*)d_in[1];
        scores = (const float*)d_in[0];
    }
    float* out = (float*)d_out;

    cudaFuncSetAttribute(k_cold,    cudaFuncAttributeMaxDynamicSharedMemorySize, HWORDS * 4);
    cudaFuncSetAttribute(k_sortnms, cudaFuncAttributeMaxDynamicSharedMemorySize, CAP * 8);

    k_scan   <<<dim3(HSLICES, NB), 1024>>>((const float4*)scores);
    k_cold   <<<NB, 1024, HWORDS * 4>>>((const float4*)scores);
    k_sortnms<<<NB, 1024, CAP * 8>>>((const float4*)boxes, out);
}